// round 1
// baseline (speedup 1.0000x reference)
#include <cuda_runtime.h>
#include <cstdint>

// Problem dims (fixed by the dataset)
#define T_STEPS 32
#define B_DIM   256
#define F_DIM   2048
#define H_DIM   4096
#define M_DIM   (T_STEPS * B_DIM)   // 8192
#define K_DIM   F_DIM               // 2048
#define N_DIM   H_DIM               // 4096
#define BH      (B_DIM * H_DIM)     // 1048576

// 128 MiB scratch for the current tensor cur[T*B, H] (allowed: __device__ global)
__device__ float g_cur[(size_t)M_DIM * N_DIM];

// ---------------------------------------------------------------------------
// Kernel 1: fp32 SGEMM  C[M,N] = A[M,K] @ W[N,K]^T + bias[N]
// 128x128 block tile, BK=16, 256 threads, 8x8 per-thread micro-tile.
// ---------------------------------------------------------------------------
#define BM 128
#define BN 128
#define BK 16
#define TM 8
#define TN 8
#define PAD 4   // smem row pad: stride 132 -> mostly conflict-free

__global__ __launch_bounds__(256, 2)
void gemm_fp32_kernel(const float* __restrict__ A,
                      const float* __restrict__ W,
                      const float* __restrict__ bias)
{
    __shared__ float As[BK][BM + PAD];
    __shared__ float Bs[BK][BN + PAD];

    const int tid = threadIdx.x;
    const int tx  = tid & 15;   // 0..15 -> N direction
    const int ty  = tid >> 4;   // 0..15 -> M direction

    const int rowBase = blockIdx.y * BM;
    const int colBase = blockIdx.x * BN;

    const float* Ap = A + (size_t)rowBase * K_DIM;
    const float* Wp = W + (size_t)colBase * K_DIM;

    float acc[TM][TN];
#pragma unroll
    for (int i = 0; i < TM; i++)
#pragma unroll
        for (int j = 0; j < TN; j++)
            acc[i][j] = 0.0f;

    for (int k0 = 0; k0 < K_DIM; k0 += BK) {
        // Load A tile (128 rows x 16 k) and W tile, transposed into smem.
        // Each thread: 2 x float4 from A, 2 x float4 from W.
#pragma unroll
        for (int it = 0; it < 2; it++) {
            int idx = tid + it * 256;        // 0..511
            int r   = idx >> 2;              // row within tile 0..127
            int kq  = (idx & 3) << 2;        // k offset 0,4,8,12

            float4 va = *(const float4*)(Ap + (size_t)r * K_DIM + k0 + kq);
            As[kq + 0][r] = va.x;
            As[kq + 1][r] = va.y;
            As[kq + 2][r] = va.z;
            As[kq + 3][r] = va.w;

            float4 vw = *(const float4*)(Wp + (size_t)r * K_DIM + k0 + kq);
            Bs[kq + 0][r] = vw.x;
            Bs[kq + 1][r] = vw.y;
            Bs[kq + 2][r] = vw.z;
            Bs[kq + 3][r] = vw.w;
        }
        __syncthreads();

#pragma unroll
        for (int k = 0; k < BK; k++) {
            float a[TM], bb[TN];
#pragma unroll
            for (int i = 0; i < TM; i += 4) {
                float4 t4 = *(const float4*)&As[k][ty * TM + i];
                a[i + 0] = t4.x; a[i + 1] = t4.y; a[i + 2] = t4.z; a[i + 3] = t4.w;
            }
#pragma unroll
            for (int j = 0; j < TN; j += 4) {
                float4 t4 = *(const float4*)&Bs[k][tx * TN + j];
                bb[j + 0] = t4.x; bb[j + 1] = t4.y; bb[j + 2] = t4.z; bb[j + 3] = t4.w;
            }
#pragma unroll
            for (int i = 0; i < TM; i++)
#pragma unroll
                for (int j = 0; j < TN; j++)
                    acc[i][j] = fmaf(a[i], bb[j], acc[i][j]);
        }
        __syncthreads();
    }

    // Epilogue: add bias, store to scratch (float4).
#pragma unroll
    for (int i = 0; i < TM; i++) {
        int row = rowBase + ty * TM + i;
        float* Cp = g_cur + (size_t)row * N_DIM + colBase + tx * TN;
#pragma unroll
        for (int j = 0; j < TN; j += 4) {
            int col = colBase + tx * TN + j;
            float4 v;
            v.x = acc[i][j + 0] + bias[col + 0];
            v.y = acc[i][j + 1] + bias[col + 1];
            v.z = acc[i][j + 2] + bias[col + 2];
            v.w = acc[i][j + 3] + bias[col + 3];
            *(float4*)(Cp + j) = v;
        }
    }
}

// ---------------------------------------------------------------------------
// Kernel 2: LIF scan over T per (b,h).
// v <- v + (x - v)/2 ; spk = (v >= 1) ; v <- spk ? 0 : v
// out layout: spk_seq [T,B,H] then count [B,H]
// ---------------------------------------------------------------------------
__global__ __launch_bounds__(256)
void lif_kernel(float* __restrict__ out)
{
    int i = blockIdx.x * blockDim.x + threadIdx.x;
    if (i >= BH) return;

    float v = 0.0f;
    float cnt = 0.0f;
#pragma unroll
    for (int t = 0; t < T_STEPS; t++) {
        float x = g_cur[(size_t)t * BH + i];
        // replicate reference rounding: v + (x - v) / 2  (no FMA contraction)
        v = __fadd_rn(v, __fmul_rn(__fsub_rn(x, v), 0.5f));
        bool fire = (v >= 1.0f);
        float spk = fire ? 1.0f : 0.0f;
        out[(size_t)t * BH + i] = spk;
        cnt += spk;
        v = fire ? 0.0f : v;
    }
    out[(size_t)T_STEPS * BH + i] = cnt;
}

// ---------------------------------------------------------------------------
extern "C" void kernel_launch(void* const* d_in, const int* in_sizes, int n_in,
                              void* d_out, int out_size)
{
    const float* x_seq = (const float*)d_in[0];  // [T,B,F]
    const float* W     = (const float*)d_in[1];  // [H,F]
    const float* b     = (const float*)d_in[2];  // [H]
    float* out = (float*)d_out;

    dim3 gemm_grid(N_DIM / BN, M_DIM / BM);      // (32, 64)
    gemm_fp32_kernel<<<gemm_grid, 256>>>(x_seq, W, b);

    lif_kernel<<<(BH + 255) / 256, 256>>>(out);
}

// round 5
// speedup vs baseline: 1.0824x; 1.0824x over previous
#include <cuda_runtime.h>
#include <cstdint>

// ---------------------------------------------------------------- dims
#define T_STEPS 32
#define B_DIM   256
#define F_DIM   2048
#define H_DIM   4096
#define M_DIM   (T_STEPS * B_DIM)   // 8192
#define K_DIM   F_DIM               // 2048
#define N_DIM   H_DIM               // 4096
#define BH      (B_DIM * H_DIM)     // 1048576

// scratch for cur[T*B, H]
__device__ float g_cur[(size_t)M_DIM * N_DIM];   // 128 MB

// ---------------------------------------------------------------- GEMM
// C[M,N] = A[M,K] @ W[N,K]^T + bias[N]
// 128x128 tile, BK=16, 256 threads, 8x8 micro-tile.
// Register-staged double buffering: LDG(i+1) overlaps compute(i).
// Accumulation: per-output single fp32 accumulator, k strictly ascending,
// fmaf each step -> bit-identical to the round-1 kernel (rel_err 0.0).
#define BM  128
#define BN  128
#define BK  16
#define PAD 4

__global__ __launch_bounds__(256, 2)
void gemm_fp32_db(const float* __restrict__ A,
                  const float* __restrict__ W,
                  const float* __restrict__ bias)
{
    __shared__ float As[2][BK][BM + PAD];
    __shared__ float Bs[2][BK][BM + PAD];

    const int tid = threadIdx.x;
    const int tx  = tid & 15;    // N direction
    const int ty  = tid >> 4;    // M direction

    const int rowBase = blockIdx.y * BM;
    const int colBase = blockIdx.x * BN;

    // loader indices: idx = tid + it*256, r = idx>>2, kq = (idx&3)*4
    const int r0 = tid >> 2;          // 0..63
    const int r1 = r0 + 64;           // 64..127
    const int kq = (tid & 3) << 2;    // 0,4,8,12

    const float* ApA = A + (size_t)(rowBase + r0) * K_DIM + kq;
    const float* ApB = A + (size_t)(rowBase + r1) * K_DIM + kq;
    const float* WpA = W + (size_t)(colBase + r0) * K_DIM + kq;
    const float* WpB = W + (size_t)(colBase + r1) * K_DIM + kq;

    float acc[8][8];
#pragma unroll
    for (int i = 0; i < 8; i++)
#pragma unroll
        for (int j = 0; j < 8; j++) acc[i][j] = 0.0f;

    // prologue: LDG chunk 0, STS into buf 0
    float4 av0 = *(const float4*)(ApA);
    float4 av1 = *(const float4*)(ApB);
    float4 bv0 = *(const float4*)(WpA);
    float4 bv1 = *(const float4*)(WpB);
    {
        As[0][kq + 0][r0] = av0.x; As[0][kq + 1][r0] = av0.y;
        As[0][kq + 2][r0] = av0.z; As[0][kq + 3][r0] = av0.w;
        As[0][kq + 0][r1] = av1.x; As[0][kq + 1][r1] = av1.y;
        As[0][kq + 2][r1] = av1.z; As[0][kq + 3][r1] = av1.w;
        Bs[0][kq + 0][r0] = bv0.x; Bs[0][kq + 1][r0] = bv0.y;
        Bs[0][kq + 2][r0] = bv0.z; Bs[0][kq + 3][r0] = bv0.w;
        Bs[0][kq + 0][r1] = bv1.x; Bs[0][kq + 1][r1] = bv1.y;
        Bs[0][kq + 2][r1] = bv1.z; Bs[0][kq + 3][r1] = bv1.w;
    }
    __syncthreads();

    const int NIT = K_DIM / BK;   // 128
    for (int i = 0; i < NIT; i++) {
        const int cur = i & 1;
        const int nxt = cur ^ 1;

        // issue next chunk's global loads early (latency hidden by compute)
        if (i + 1 < NIT) {
            const size_t off = (size_t)(i + 1) * BK;
            av0 = *(const float4*)(ApA + off);
            av1 = *(const float4*)(ApB + off);
            bv0 = *(const float4*)(WpA + off);
            bv1 = *(const float4*)(WpB + off);
        }

        // compute on current buffer; k ascending, single accumulator
#pragma unroll
        for (int k = 0; k < BK; k++) {
            float a[8], b[8];
            float4 t0 = *(const float4*)&As[cur][k][ty * 8];
            float4 t1 = *(const float4*)&As[cur][k][ty * 8 + 4];
            a[0] = t0.x; a[1] = t0.y; a[2] = t0.z; a[3] = t0.w;
            a[4] = t1.x; a[5] = t1.y; a[6] = t1.z; a[7] = t1.w;
            float4 u0 = *(const float4*)&Bs[cur][k][tx * 8];
            float4 u1 = *(const float4*)&Bs[cur][k][tx * 8 + 4];
            b[0] = u0.x; b[1] = u0.y; b[2] = u0.z; b[3] = u0.w;
            b[4] = u1.x; b[5] = u1.y; b[6] = u1.z; b[7] = u1.w;
#pragma unroll
            for (int ii = 0; ii < 8; ii++)
#pragma unroll
                for (int jj = 0; jj < 8; jj++)
                    acc[ii][jj] = fmaf(a[ii], b[jj], acc[ii][jj]);
        }

        // store next chunk into the other buffer
        if (i + 1 < NIT) {
            As[nxt][kq + 0][r0] = av0.x; As[nxt][kq + 1][r0] = av0.y;
            As[nxt][kq + 2][r0] = av0.z; As[nxt][kq + 3][r0] = av0.w;
            As[nxt][kq + 0][r1] = av1.x; As[nxt][kq + 1][r1] = av1.y;
            As[nxt][kq + 2][r1] = av1.z; As[nxt][kq + 3][r1] = av1.w;
            Bs[nxt][kq + 0][r0] = bv0.x; Bs[nxt][kq + 1][r0] = bv0.y;
            Bs[nxt][kq + 2][r0] = bv0.z; Bs[nxt][kq + 3][r0] = bv0.w;
            Bs[nxt][kq + 0][r1] = bv1.x; Bs[nxt][kq + 1][r1] = bv1.y;
            Bs[nxt][kq + 2][r1] = bv1.z; Bs[nxt][kq + 3][r1] = bv1.w;
        }
        __syncthreads();
    }

    // epilogue: add bias (single fp32 add, same as round 1), store
#pragma unroll
    for (int i = 0; i < 8; i++) {
        int row = rowBase + ty * 8 + i;
        float* Cp = g_cur + (size_t)row * N_DIM + colBase + tx * 8;
#pragma unroll
        for (int j = 0; j < 8; j += 4) {
            int col = colBase + tx * 8 + j;
            float4 v;
            v.x = acc[i][j + 0] + bias[col + 0];
            v.y = acc[i][j + 1] + bias[col + 1];
            v.z = acc[i][j + 2] + bias[col + 2];
            v.w = acc[i][j + 3] + bias[col + 3];
            *(float4*)(Cp + j) = v;
        }
    }
}

// ---------------------------------------------------------------- LIF scan
// v <- v + (x - v)/2 ; spk = (v >= 1) ; v <- spk ? 0 : v
__global__ __launch_bounds__(256)
void lif_kernel(float* __restrict__ out)
{
    int i4 = blockIdx.x * blockDim.x + threadIdx.x;
    if (i4 >= BH / 4) return;

    const float4* cur4 = (const float4*)g_cur;
    float4* out4 = (float4*)out;

    float v0 = 0.f, v1 = 0.f, v2 = 0.f, v3 = 0.f;
    float c0 = 0.f, c1 = 0.f, c2 = 0.f, c3 = 0.f;
#pragma unroll
    for (int t = 0; t < T_STEPS; t++) {
        float4 x = cur4[(size_t)t * (BH / 4) + i4];
        float4 s;
        v0 = __fadd_rn(v0, __fmul_rn(__fsub_rn(x.x, v0), 0.5f));
        v1 = __fadd_rn(v1, __fmul_rn(__fsub_rn(x.y, v1), 0.5f));
        v2 = __fadd_rn(v2, __fmul_rn(__fsub_rn(x.z, v2), 0.5f));
        v3 = __fadd_rn(v3, __fmul_rn(__fsub_rn(x.w, v3), 0.5f));
        bool f0 = v0 >= 1.0f, f1 = v1 >= 1.0f, f2 = v2 >= 1.0f, f3 = v3 >= 1.0f;
        s.x = f0 ? 1.f : 0.f; s.y = f1 ? 1.f : 0.f;
        s.z = f2 ? 1.f : 0.f; s.w = f3 ? 1.f : 0.f;
        out4[(size_t)t * (BH / 4) + i4] = s;
        c0 += s.x; c1 += s.y; c2 += s.z; c3 += s.w;
        v0 = f0 ? 0.f : v0; v1 = f1 ? 0.f : v1;
        v2 = f2 ? 0.f : v2; v3 = f3 ? 0.f : v3;
    }
    out4[(size_t)T_STEPS * (BH / 4) + i4] = make_float4(c0, c1, c2, c3);
}

// ---------------------------------------------------------------- launch
extern "C" void kernel_launch(void* const* d_in, const int* in_sizes, int n_in,
                              void* d_out, int out_size)
{
    const float* x_seq = (const float*)d_in[0];  // [T,B,F]
    const float* W     = (const float*)d_in[1];  // [H,F]
    const float* b     = (const float*)d_in[2];  // [H]
    float* out = (float*)d_out;

    dim3 gg(N_DIM / BN, M_DIM / BM);   // (32, 64)
    gemm_fp32_db<<<gg, 256>>>(x_seq, W, b);

    lif_kernel<<<(BH / 4 + 255) / 256, 256>>>(out);
}